// round 9
// baseline (speedup 1.0000x reference)
#include <cuda_runtime.h>
#include <cuda_bf16.h>
#include <mma.h>
#include <math.h>
#include <cstdint>

using namespace nvcuda;
typedef __nv_bfloat16 bf16;

#define SEQ   2048
#define DMOD  1024
#define NHEAD 16
#define HDIM  64
#define DMLP  8192

// ---------------- scratch -----------------------------------------------------
__device__ float g_qkv[SEQ * 3 * DMOD];
__device__ float g_h  [SEQ * DMOD];
__device__ float g_g  [SEQ * DMLP];
__device__ bf16  g_xnh[SEQ * DMOD],      g_xnl[SEQ * DMOD];
__device__ bf16  g_ath[SEQ * DMOD],      g_atl[SEQ * DMOD];
__device__ bf16  g_hnh[SEQ * DMOD],      g_hnl[SEQ * DMOD];
__device__ bf16  g_mph[SEQ * DMLP / 2],  g_mpl[SEQ * DMLP / 2];
__device__ bf16  g_Wah[3 * DMOD * DMOD], g_Wal[3 * DMOD * DMOD];
__device__ bf16  g_Woh[DMOD * DMOD],     g_Wol[DMOD * DMOD];
__device__ bf16  g_Wph[DMLP * DMOD],     g_Wpl[DMLP * DMOD];
__device__ bf16  g_Wfh[DMOD * DMLP / 2], g_Wfl[DMOD * DMLP / 2];

__device__ __forceinline__ void split_hl(float v, bf16& h, bf16& l) {
    h = __float2bfloat16(v);
    l = __float2bfloat16(v - __bfloat162float(h));
}

__device__ __forceinline__ void cp16(bf16* dst, const bf16* src) {
    uint32_t s = (uint32_t)__cvta_generic_to_shared(dst);
    asm volatile("cp.async.cg.shared.global [%0], [%1], 16;\n" :: "r"(s), "l"(src));
}

// ---------------- weight fp32 -> bf16 hi/lo (vectorized) -----------------------
__global__ void __launch_bounds__(256) cvt_hilo(const float* __restrict__ s,
                                                bf16* __restrict__ h,
                                                bf16* __restrict__ l, int n) {
    int i = (blockIdx.x * 256 + threadIdx.x) * 8;
    if (i >= n) return;
    float4 v0 = *(const float4*)(s + i);
    float4 v1 = *(const float4*)(s + i + 4);
    float a[8] = {v0.x, v0.y, v0.z, v0.w, v1.x, v1.y, v1.z, v1.w};
    __align__(16) bf16 hh[8];
    __align__(16) bf16 ll[8];
    #pragma unroll
    for (int e = 0; e < 8; e++) split_hl(a[e], hh[e], ll[e]);
    *(uint4*)(h + i) = *(uint4*)hh;
    *(uint4*)(l + i) = *(uint4*)ll;
}

// ---------------- LayerNorm -> bf16 hi/lo -------------------------------------
__global__ void __launch_bounds__(256) ln_kernel(const float* __restrict__ x,
                                                 bf16* __restrict__ yh,
                                                 bf16* __restrict__ yl) {
    __shared__ float row[DMOD];
    __shared__ float red[256];
    const int r   = blockIdx.x;
    const int tid = threadIdx.x;
    const float* xr = x + (long)r * DMOD;

    float s = 0.f;
    #pragma unroll
    for (int i = 0; i < 4; i++) {
        float v = xr[tid + i * 256];
        row[tid + i * 256] = v;
        s += v;
    }
    red[tid] = s; __syncthreads();
    #pragma unroll
    for (int off = 128; off > 0; off >>= 1) {
        if (tid < off) red[tid] += red[tid + off];
        __syncthreads();
    }
    const float mu = red[0] * (1.f / DMOD);
    __syncthreads();

    float ss = 0.f;
    #pragma unroll
    for (int i = 0; i < 4; i++) {
        float d = row[tid + i * 256] - mu;
        ss += d * d;
    }
    red[tid] = ss; __syncthreads();
    #pragma unroll
    for (int off = 128; off > 0; off >>= 1) {
        if (tid < off) red[tid] += red[tid + off];
        __syncthreads();
    }
    const float inv = rsqrtf(red[0] * (1.f / DMOD) + 1e-5f);

    #pragma unroll
    for (int i = 0; i < 4; i++) {
        int c = tid + i * 256;
        split_hl((row[c] - mu) * inv, yh[(long)r * DMOD + c], yl[(long)r * DMOD + c]);
    }
}

// ---------------- GEMM 128x128 (small-N): 3-pass split, cp.async 2-stage ------
#define GBK   32
#define PADK  40
#define GEMM_SMEM (2 * 4 * 128 * PADK * (int)sizeof(bf16))   // 81920 B

__global__ void __launch_bounds__(256, 2) gemm_pre(
    const bf16* __restrict__ Ah, const bf16* __restrict__ Al, int lda,
    const bf16* __restrict__ Bh, const bf16* __restrict__ Bl, int ldb,
    float* __restrict__ C, int ldc, const float* __restrict__ Res, int K)
{
    extern __shared__ bf16 sm[];
    const int tid  = threadIdx.x;
    const int m0   = blockIdx.y * 128;
    const int n0   = blockIdx.x * 128;
    const int warp = tid >> 5;
    const int wm0  = (warp & 3) * 32;
    const int wn0  = (warp >> 2) * 64;

    wmma::fragment<wmma::accumulator, 16, 16, 16, float> acc[2][4];
    #pragma unroll
    for (int i = 0; i < 2; i++)
        #pragma unroll
        for (int j = 0; j < 4; j++) {
            if (Res) {
                const float* rp = Res + (long)(m0 + wm0 + 16 * i) * ldc
                                      + n0 + wn0 + 16 * j;
                wmma::load_matrix_sync(acc[i][j], rp, ldc, wmma::mem_row_major);
            } else {
                wmma::fill_fragment(acc[i][j], 0.f);
            }
        }

    const bf16* base0 = Ah + (long)m0 * lda;
    const bf16* base1 = Al + (long)m0 * lda;
    const bf16* base2 = Bh + (long)n0 * ldb;
    const bf16* base3 = Bl + (long)n0 * ldb;

    #define LOAD_STAGE(ST, K0)                                                 \
    do {                                                                       \
        bf16* sb = sm + (ST) * (4 * 128 * PADK);                               \
        _Pragma("unroll")                                                      \
        for (int t = 0; t < 8; t++) {                                          \
            int c   = tid + t * 256;                                           \
            int arr = c >> 9;                                                  \
            int rem = c & 511;                                                 \
            int row = rem >> 2;                                                \
            int col = (rem & 3) * 8;                                           \
            const bf16* src =                                                  \
                (arr == 0) ? base0 + (long)row * lda + (K0) + col :            \
                (arr == 1) ? base1 + (long)row * lda + (K0) + col :            \
                (arr == 2) ? base2 + (long)row * ldb + (K0) + col :            \
                             base3 + (long)row * ldb + (K0) + col;             \
            cp16(sb + arr * (128 * PADK) + row * PADK + col, src);             \
        }                                                                      \
    } while (0)

    const int nk = K / GBK;
    LOAD_STAGE(0, 0);
    asm volatile("cp.async.commit_group;\n" ::);

    for (int ks = 0; ks < nk; ks++) {
        asm volatile("cp.async.wait_group 0;\n" ::);
        __syncthreads();
        if (ks + 1 < nk) {
            LOAD_STAGE((ks + 1) & 1, (ks + 1) * GBK);
            asm volatile("cp.async.commit_group;\n" ::);
        }
        bf16* sb  = sm + (ks & 1) * (4 * 128 * PADK);
        bf16* sAh = sb;
        bf16* sAl = sb + 128 * PADK;
        bf16* sBh = sb + 2 * 128 * PADK;
        bf16* sBl = sb + 3 * 128 * PADK;

        #pragma unroll
        for (int k16 = 0; k16 < GBK; k16 += 16) {
            wmma::fragment<wmma::matrix_a, 16, 16, 16, bf16, wmma::row_major> ah[2], al[2];
            #pragma unroll
            for (int i = 0; i < 2; i++) {
                wmma::load_matrix_sync(ah[i], sAh + (wm0 + 16 * i) * PADK + k16, PADK);
                wmma::load_matrix_sync(al[i], sAl + (wm0 + 16 * i) * PADK + k16, PADK);
            }
            #pragma unroll
            for (int j = 0; j < 4; j++) {
                wmma::fragment<wmma::matrix_b, 16, 16, 16, bf16, wmma::col_major> bh, bl;
                wmma::load_matrix_sync(bh, sBh + (wn0 + 16 * j) * PADK + k16, PADK);
                wmma::load_matrix_sync(bl, sBl + (wn0 + 16 * j) * PADK + k16, PADK);
                #pragma unroll
                for (int i = 0; i < 2; i++) {
                    wmma::mma_sync(acc[i][j], ah[i], bl, acc[i][j]);
                    wmma::mma_sync(acc[i][j], al[i], bh, acc[i][j]);
                    wmma::mma_sync(acc[i][j], ah[i], bh, acc[i][j]);
                }
            }
        }
    }

    #pragma unroll
    for (int i = 0; i < 2; i++)
        #pragma unroll
        for (int j = 0; j < 4; j++) {
            float* cp = C + (long)(m0 + wm0 + 16 * i) * ldc + n0 + wn0 + 16 * j;
            wmma::store_matrix_sync(cp, acc[i][j], ldc, wmma::mem_row_major);
        }
}

// ---------------- GEMM 128x256 (big-N): warp tile 64x64 -----------------------
#define BGM 128
#define BGN 256
#define BIG_STAGE ((2 * BGM + 2 * BGN) * PADK)                 // elements
#define BIG_SMEM  (2 * BIG_STAGE * (int)sizeof(bf16))          // 122880 B

__global__ void __launch_bounds__(256, 1) gemm_big(
    const bf16* __restrict__ Ah, const bf16* __restrict__ Al, int lda,
    const bf16* __restrict__ Bh, const bf16* __restrict__ Bl, int ldb,
    float* __restrict__ C, int ldc, int K)
{
    extern __shared__ bf16 sm[];
    const int tid  = threadIdx.x;
    const int m0   = blockIdx.y * BGM;
    const int n0   = blockIdx.x * BGN;
    const int warp = tid >> 5;
    const int wm0  = (warp & 1) * 64;    // 2 warp rows
    const int wn0  = (warp >> 1) * 64;   // 4 warp cols

    wmma::fragment<wmma::accumulator, 16, 16, 16, float> acc[4][4];
    #pragma unroll
    for (int i = 0; i < 4; i++)
        #pragma unroll
        for (int j = 0; j < 4; j++) wmma::fill_fragment(acc[i][j], 0.f);

    const bf16* bA0 = Ah + (long)m0 * lda;
    const bf16* bA1 = Al + (long)m0 * lda;
    const bf16* bB0 = Bh + (long)n0 * ldb;
    const bf16* bB1 = Bl + (long)n0 * ldb;

    // per stage (16B chunks): Ah 512, Al 512, Bh 1024, Bl 1024 -> 12/thread
    #define BIG_LOAD(ST, K0)                                                    \
    do {                                                                        \
        bf16* sb = sm + (ST) * BIG_STAGE;                                       \
        _Pragma("unroll")                                                       \
        for (int t = 0; t < 2; t++) {                                           \
            int c = tid + t * 256;                                              \
            int row = c >> 2, col = (c & 3) * 8;                                \
            cp16(sb + row * PADK + col, bA0 + (long)row * lda + (K0) + col);    \
            cp16(sb + BGM * PADK + row * PADK + col,                            \
                 bA1 + (long)row * lda + (K0) + col);                           \
        }                                                                       \
        _Pragma("unroll")                                                       \
        for (int t = 0; t < 4; t++) {                                           \
            int c = tid + t * 256;                                              \
            int row = c >> 2, col = (c & 3) * 8;                                \
            cp16(sb + 2 * BGM * PADK + row * PADK + col,                        \
                 bB0 + (long)row * ldb + (K0) + col);                           \
            cp16(sb + (2 * BGM + BGN) * PADK + row * PADK + col,                \
                 bB1 + (long)row * ldb + (K0) + col);                           \
        }                                                                       \
        asm volatile("cp.async.commit_group;\n" ::);                            \
    } while (0)

    const int nk = K / GBK;
    BIG_LOAD(0, 0);

    for (int ks = 0; ks < nk; ks++) {
        asm volatile("cp.async.wait_group 0;\n" ::);
        __syncthreads();
        if (ks + 1 < nk) BIG_LOAD((ks + 1) & 1, (ks + 1) * GBK);

        bf16* sb  = sm + (ks & 1) * BIG_STAGE;
        bf16* sAh = sb;
        bf16* sAl = sb + BGM * PADK;
        bf16* sBh = sb + 2 * BGM * PADK;
        bf16* sBl = sb + (2 * BGM + BGN) * PADK;

        #pragma unroll
        for (int k16 = 0; k16 < GBK; k16 += 16) {
            wmma::fragment<wmma::matrix_a, 16, 16, 16, bf16, wmma::row_major> ah[4], al[4];
            #pragma unroll
            for (int i = 0; i < 4; i++) {
                wmma::load_matrix_sync(ah[i], sAh + (wm0 + 16 * i) * PADK + k16, PADK);
                wmma::load_matrix_sync(al[i], sAl + (wm0 + 16 * i) * PADK + k16, PADK);
            }
            #pragma unroll
            for (int j = 0; j < 4; j++) {
                wmma::fragment<wmma::matrix_b, 16, 16, 16, bf16, wmma::col_major> bh, bl;
                wmma::load_matrix_sync(bh, sBh + (wn0 + 16 * j) * PADK + k16, PADK);
                wmma::load_matrix_sync(bl, sBl + (wn0 + 16 * j) * PADK + k16, PADK);
                #pragma unroll
                for (int i = 0; i < 4; i++) {
                    wmma::mma_sync(acc[i][j], ah[i], bl, acc[i][j]);
                    wmma::mma_sync(acc[i][j], al[i], bh, acc[i][j]);
                    wmma::mma_sync(acc[i][j], ah[i], bh, acc[i][j]);
                }
            }
        }
    }

    #pragma unroll
    for (int i = 0; i < 4; i++)
        #pragma unroll
        for (int j = 0; j < 4; j++) {
            float* cp = C + (long)(m0 + wm0 + 16 * i) * ldc + n0 + wn0 + 16 * j;
            wmma::store_matrix_sync(cp, acc[i][j], ldc, wmma::mem_row_major);
        }
}

// ---------------- RoPE --------------------------------------------------------
__global__ void rope_kernel(float* __restrict__ qkv) {
    const int idx = blockIdx.x * 256 + threadIdx.x;
    if (idx >= SEQ * NHEAD * 32) return;
    const int j = idx & 31;
    const int h = (idx >> 5) & (NHEAD - 1);
    const int l = idx >> 9;

    const float inv_freq = powf(10000.f, -(float)j / 32.f);
    const float ang = (float)l * inv_freq;
    float c, s;
    sincosf(ang, &s, &c);

    float* qp = qkv + (long)l * (3 * DMOD) + h * HDIM + j;
    float q1 = qp[0], q2 = qp[32];
    qp[0]  = q1 * c - q2 * s;
    qp[32] = q2 * c + q1 * s;

    float* kp = qp + DMOD;
    float k1 = kp[0], k2 = kp[32];
    kp[0]  = k1 * c - k2 * s;
    kp[32] = k2 * c + k1 * s;
}

// ---------------- Flash attention on tensor cores (hi/lo output) --------------
#define BSTR 72
#define FSTR 68
#define ATW_SMEM (4 * 64 * BSTR * 2 + 2 * 64 * FSTR * 4)

__global__ void __launch_bounds__(256, 2) attn_wmma(const float* __restrict__ qkv,
                                                    bf16* __restrict__ outh,
                                                    bf16* __restrict__ outl) {
    extern __shared__ char smraw[];
    bf16* Kh = (bf16*)smraw;
    bf16* Kl = Kh + 64 * BSTR;
    bf16* Vh = Kl + 64 * BSTR;
    bf16* Vl = Vh + 64 * BSTR;
    float* Sf = (float*)(Vl + 64 * BSTR);
    float* Of = Sf + 64 * FSTR;
    bf16* Ph = Kh;
    bf16* Pl = Kl;

    const int h     = blockIdx.x;
    const int qb    = (int)gridDim.y - 1 - (int)blockIdx.y;
    const int tid   = threadIdx.x;
    const int warp  = tid >> 5;
    const int qbase = qb * 64;
    const int rt    = warp >> 1;
    const int chalf = (warp & 1) * 32;

    #pragma unroll
    for (int it = 0; it < 16; it++) {
        int idx = tid + it * 256;
        int row = idx >> 6, col = idx & 63;
        float v = qkv[(long)(qbase + row) * (3 * DMOD) + h * HDIM + col] * 0.125f;
        split_hl(v, Kh[row * BSTR + col], Kl[row * BSTR + col]);
    }
    __syncthreads();
    wmma::fragment<wmma::matrix_a, 16, 16, 16, bf16, wmma::row_major> qh[4], ql[4];
    #pragma unroll
    for (int ks = 0; ks < 4; ks++) {
        wmma::load_matrix_sync(qh[ks], Kh + rt * 16 * BSTR + ks * 16, BSTR);
        wmma::load_matrix_sync(ql[ks], Kl + rt * 16 * BSTR + ks * 16, BSTR);
    }
    #pragma unroll
    for (int it = 0; it < 16; it++) {
        int idx = tid + it * 256;
        Of[(idx >> 6) * FSTR + (idx & 63)] = 0.f;
    }
    __syncthreads();

    const int r  = tid >> 2;
    const int cs = (tid & 3) * 16;
    float mrow = -1e30f, lsum = 0.f, alpha = 0.f;

    for (int kb = 0; kb <= qb; kb++) {
        const int kbase = kb * 64;

        #pragma unroll
        for (int it = 0; it < 16; it++) {
            int idx = tid + it * 256;
            int row = idx >> 6, col = idx & 63;
            long base = (long)(kbase + row) * (3 * DMOD) + h * HDIM + col;
            split_hl(qkv[base + DMOD],     Kh[row * BSTR + col], Kl[row * BSTR + col]);
            split_hl(qkv[base + 2 * DMOD], Vh[row * BSTR + col], Vl[row * BSTR + col]);
        }
        __syncthreads();

        #pragma unroll
        for (int ct = 0; ct < 2; ct++) {
            const int col0 = chalf + ct * 16;
            wmma::fragment<wmma::accumulator, 16, 16, 16, float> acc;
            wmma::fill_fragment(acc, 0.f);
            #pragma unroll
            for (int ks = 0; ks < 4; ks++) {
                wmma::fragment<wmma::matrix_b, 16, 16, 16, bf16, wmma::col_major> bh, bl;
                wmma::load_matrix_sync(bh, Kh + col0 * BSTR + ks * 16, BSTR);
                wmma::load_matrix_sync(bl, Kl + col0 * BSTR + ks * 16, BSTR);
                wmma::mma_sync(acc, qh[ks], bl, acc);
                wmma::mma_sync(acc, ql[ks], bh, acc);
                wmma::mma_sync(acc, qh[ks], bh, acc);
            }
            wmma::store_matrix_sync(Sf + rt * 16 * FSTR + col0, acc, FSTR,
                                    wmma::mem_row_major);
        }
        __syncthreads();

        float s[16];
        #pragma unroll
        for (int j = 0; j < 16; j++) s[j] = Sf[r * FSTR + cs + j];
        if (kb == qb) {
            #pragma unroll
            for (int j = 0; j < 16; j++)
                if (kbase + cs + j > qbase + r) s[j] = -1e30f;
        }
        float mloc = s[0];
        #pragma unroll
        for (int j = 1; j < 16; j++) mloc = fmaxf(mloc, s[j]);
        mloc = fmaxf(mloc, __shfl_xor_sync(0xffffffffu, mloc, 1));
        mloc = fmaxf(mloc, __shfl_xor_sync(0xffffffffu, mloc, 2));
        const float mnew = fmaxf(mrow, mloc);
        alpha = __expf(mrow - mnew);

        float ps = 0.f;
        #pragma unroll
        for (int j = 0; j < 16; j++) {
            float p = __expf(s[j] - mnew);
            ps += p;
            split_hl(p, Ph[r * BSTR + cs + j], Pl[r * BSTR + cs + j]);
        }
        ps += __shfl_xor_sync(0xffffffffu, ps, 1);
        ps += __shfl_xor_sync(0xffffffffu, ps, 2);
        lsum = lsum * alpha + ps;
        mrow = mnew;
        __syncthreads();

        #pragma unroll
        for (int ct = 0; ct < 2; ct++) {
            const int col0 = chalf + ct * 16;
            wmma::fragment<wmma::accumulator, 16, 16, 16, float> acc;
            wmma::fill_fragment(acc, 0.f);
            #pragma unroll
            for (int js = 0; js < 4; js++) {
                wmma::fragment<wmma::matrix_a, 16, 16, 16, bf16, wmma::row_major> ph, pl;
                wmma::load_matrix_sync(ph, Ph + rt * 16 * BSTR + js * 16, BSTR);
                wmma::load_matrix_sync(pl, Pl + rt * 16 * BSTR + js * 16, BSTR);
                wmma::fragment<wmma::matrix_b, 16, 16, 16, bf16, wmma::row_major> vh, vl;
                wmma::load_matrix_sync(vh, Vh + js * 16 * BSTR + col0, BSTR);
                wmma::load_matrix_sync(vl, Vl + js * 16 * BSTR + col0, BSTR);
                wmma::mma_sync(acc, ph, vl, acc);
                wmma::mma_sync(acc, pl, vh, acc);
                wmma::mma_sync(acc, ph, vh, acc);
            }
            wmma::store_matrix_sync(Sf + rt * 16 * FSTR + col0, acc, FSTR,
                                    wmma::mem_row_major);
        }
        __syncthreads();

        #pragma unroll
        for (int j = 0; j < 16; j++) {
            int o = r * FSTR + cs + j;
            Of[o] = Of[o] * alpha + Sf[o];
        }
        __syncthreads();
    }

    const float invl = 1.f / lsum;
    long obase = (long)(qbase + r) * DMOD + h * HDIM + cs;
    #pragma unroll
    for (int j = 0; j < 16; j++)
        split_hl(Of[r * FSTR + cs + j] * invl, outh[obase + j], outl[obase + j]);
}

// ---------------- SwiGLU -> bf16 hi/lo -----------------------------------------
__global__ void __launch_bounds__(256) swiglu_kernel(const float* __restrict__ g,
                                                     bf16* __restrict__ oh,
                                                     bf16* __restrict__ ol) {
    const int idx = blockIdx.x * 256 + threadIdx.x;
    if (idx >= SEQ * (DMLP / 2)) return;
    const int rw = idx >> 12;
    const int c  = idx & 4095;
    const float x1 = g[(long)rw * DMLP + c];
    const float x2 = g[(long)rw * DMLP + (DMLP / 2) + c];
    const float sig = 1.f / (1.f + __expf(-x2));
    split_hl(x2 * sig * x1, oh[idx], ol[idx]);
}

// ---------------- launch --------------------------------------------------------
extern "C" void kernel_launch(void* const* d_in, const int* in_sizes, int n_in,
                              void* d_out, int out_size) {
    const float* x      = (const float*)d_in[0];
    const float* W_attn = (const float*)d_in[2];
    const float* W_out  = (const float*)d_in[3];
    const float* W_ffp  = (const float*)d_in[4];
    const float* W_ffo  = (const float*)d_in[5];
    float* out = (float*)d_out;

    float *qkv, *h, *gbuf;
    bf16 *xnh, *xnl, *ath, *atl, *hnh, *hnl, *mph, *mpl;
    bf16 *Wah, *Wal, *Woh, *Wol, *Wph, *Wpl, *Wfh, *Wfl;
    cudaGetSymbolAddress((void**)&qkv, g_qkv);
    cudaGetSymbolAddress((void**)&h,   g_h);
    cudaGetSymbolAddress((void**)&gbuf,g_g);
    cudaGetSymbolAddress((void**)&xnh, g_xnh); cudaGetSymbolAddress((void**)&xnl, g_xnl);
    cudaGetSymbolAddress((void**)&ath, g_ath); cudaGetSymbolAddress((void**)&atl, g_atl);
    cudaGetSymbolAddress((void**)&hnh, g_hnh); cudaGetSymbolAddress((void**)&hnl, g_hnl);
    cudaGetSymbolAddress((void**)&mph, g_mph); cudaGetSymbolAddress((void**)&mpl, g_mpl);
    cudaGetSymbolAddress((void**)&Wah, g_Wah); cudaGetSymbolAddress((void**)&Wal, g_Wal);
    cudaGetSymbolAddress((void**)&Woh, g_Woh); cudaGetSymbolAddress((void**)&Wol, g_Wol);
    cudaGetSymbolAddress((void**)&Wph, g_Wph); cudaGetSymbolAddress((void**)&Wpl, g_Wpl);
    cudaGetSymbolAddress((void**)&Wfh, g_Wfh); cudaGetSymbolAddress((void**)&Wfl, g_Wfl);

    cudaFuncSetAttribute(attn_wmma,
                         cudaFuncAttributeMaxDynamicSharedMemorySize, ATW_SMEM);
    cudaFuncSetAttribute(gemm_pre,
                         cudaFuncAttributeMaxDynamicSharedMemorySize, GEMM_SMEM);
    cudaFuncSetAttribute(gemm_big,
                         cudaFuncAttributeMaxDynamicSharedMemorySize, BIG_SMEM);

    // weight splits
    { int n = 3 * DMOD * DMOD; cvt_hilo<<<n / 8 / 256, 256>>>(W_attn, Wah, Wal, n); }
    { int n = DMOD * DMOD;     cvt_hilo<<<n / 8 / 256, 256>>>(W_out,  Woh, Wol, n); }
    { int n = DMLP * DMOD;     cvt_hilo<<<n / 8 / 256, 256>>>(W_ffp,  Wph, Wpl, n); }
    { int n = DMOD * DMLP / 2; cvt_hilo<<<n / 8 / 256, 256>>>(W_ffo,  Wfh, Wfl, n); }

    // 1) xn = LN(x)
    ln_kernel<<<SEQ, 256>>>(x, xnh, xnl);

    // 2) qkv = xn @ W_attn^T   (big tile)
    gemm_big<<<dim3(3 * DMOD / BGN, SEQ / BGM), 256, BIG_SMEM>>>(
        xnh, xnl, DMOD, Wah, Wal, DMOD, qkv, 3 * DMOD, DMOD);

    // 3) RoPE
    rope_kernel<<<(SEQ * NHEAD * 32 + 255) / 256, 256>>>(qkv);

    // 4) attention
    attn_wmma<<<dim3(NHEAD, SEQ / 64), 256, ATW_SMEM>>>(qkv, ath, atl);

    // 5) h = attn @ W_out^T + x
    gemm_pre<<<dim3(DMOD / 128, SEQ / 128), 256, GEMM_SMEM>>>(
        ath, atl, DMOD, Woh, Wol, DMOD, h, DMOD, x, DMOD);

    // 6) hn = LN(h)
    ln_kernel<<<SEQ, 256>>>(h, hnh, hnl);

    // 7) g = hn @ W_ffp^T   (big tile)
    gemm_big<<<dim3(DMLP / BGN, SEQ / BGM), 256, BIG_SMEM>>>(
        hnh, hnl, DMOD, Wph, Wpl, DMOD, gbuf, DMLP, DMOD);

    // 8) mlp = silu(g2)*g1
    swiglu_kernel<<<(SEQ * (DMLP / 2) + 255) / 256, 256>>>(gbuf, mph, mpl);

    // 9) out = mlp @ W_ffo^T + h
    gemm_pre<<<dim3(DMOD / 128, SEQ / 128), 256, GEMM_SMEM>>>(
        mph, mpl, DMLP / 2, Wfh, Wfl, DMLP / 2, out, DMOD, h, DMLP / 2);
}

// round 10
// speedup vs baseline: 1.0641x; 1.0641x over previous
#include <cuda_runtime.h>
#include <cuda_bf16.h>
#include <mma.h>
#include <math.h>
#include <cstdint>

using namespace nvcuda;
typedef __nv_bfloat16 bf16;

#define SEQ   2048
#define DMOD  1024
#define NHEAD 16
#define HDIM  64
#define DMLP  8192

// ---------------- scratch -----------------------------------------------------
__device__ float g_qkv[SEQ * 3 * DMOD];
__device__ float g_h  [SEQ * DMOD];
__device__ float g_g  [SEQ * DMLP];
__device__ bf16  g_xnh[SEQ * DMOD],      g_xnl[SEQ * DMOD];
__device__ bf16  g_ath[SEQ * DMOD],      g_atl[SEQ * DMOD];
__device__ bf16  g_hnh[SEQ * DMOD],      g_hnl[SEQ * DMOD];
__device__ bf16  g_mph[SEQ * DMLP / 2],  g_mpl[SEQ * DMLP / 2];
// head-major RoPE'd q/k and v, hi/lo:  [h][l][64]
__device__ bf16  g_qh[SEQ * DMOD], g_ql[SEQ * DMOD];
__device__ bf16  g_kh[SEQ * DMOD], g_kl[SEQ * DMOD];
__device__ bf16  g_vh[SEQ * DMOD], g_vl[SEQ * DMOD];
__device__ bf16  g_Wah[3 * DMOD * DMOD], g_Wal[3 * DMOD * DMOD];
__device__ bf16  g_Woh[DMOD * DMOD],     g_Wol[DMOD * DMOD];
__device__ bf16  g_Wph[DMLP * DMOD],     g_Wpl[DMLP * DMOD];
__device__ bf16  g_Wfh[DMOD * DMLP / 2], g_Wfl[DMOD * DMLP / 2];

__device__ __forceinline__ void split_hl(float v, bf16& h, bf16& l) {
    h = __float2bfloat16(v);
    l = __float2bfloat16(v - __bfloat162float(h));
}

__device__ __forceinline__ void cp16(bf16* dst, const bf16* src) {
    uint32_t s = (uint32_t)__cvta_generic_to_shared(dst);
    asm volatile("cp.async.cg.shared.global [%0], [%1], 16;\n" :: "r"(s), "l"(src));
}

// ---------------- weight fp32 -> bf16 hi/lo (vectorized) -----------------------
__global__ void __launch_bounds__(256) cvt_hilo(const float* __restrict__ s,
                                                bf16* __restrict__ h,
                                                bf16* __restrict__ l, int n) {
    int i = (blockIdx.x * 256 + threadIdx.x) * 8;
    if (i >= n) return;
    float4 v0 = *(const float4*)(s + i);
    float4 v1 = *(const float4*)(s + i + 4);
    float a[8] = {v0.x, v0.y, v0.z, v0.w, v1.x, v1.y, v1.z, v1.w};
    __align__(16) bf16 hh[8];
    __align__(16) bf16 ll[8];
    #pragma unroll
    for (int e = 0; e < 8; e++) split_hl(a[e], hh[e], ll[e]);
    *(uint4*)(h + i) = *(uint4*)hh;
    *(uint4*)(l + i) = *(uint4*)ll;
}

// ---------------- LayerNorm -> bf16 hi/lo -------------------------------------
__global__ void __launch_bounds__(256) ln_kernel(const float* __restrict__ x,
                                                 bf16* __restrict__ yh,
                                                 bf16* __restrict__ yl) {
    __shared__ float row[DMOD];
    __shared__ float red[256];
    const int r   = blockIdx.x;
    const int tid = threadIdx.x;
    const float* xr = x + (long)r * DMOD;

    float s = 0.f;
    #pragma unroll
    for (int i = 0; i < 4; i++) {
        float v = xr[tid + i * 256];
        row[tid + i * 256] = v;
        s += v;
    }
    red[tid] = s; __syncthreads();
    #pragma unroll
    for (int off = 128; off > 0; off >>= 1) {
        if (tid < off) red[tid] += red[tid + off];
        __syncthreads();
    }
    const float mu = red[0] * (1.f / DMOD);
    __syncthreads();

    float ss = 0.f;
    #pragma unroll
    for (int i = 0; i < 4; i++) {
        float d = row[tid + i * 256] - mu;
        ss += d * d;
    }
    red[tid] = ss; __syncthreads();
    #pragma unroll
    for (int off = 128; off > 0; off >>= 1) {
        if (tid < off) red[tid] += red[tid + off];
        __syncthreads();
    }
    const float inv = rsqrtf(red[0] * (1.f / DMOD) + 1e-5f);

    #pragma unroll
    for (int i = 0; i < 4; i++) {
        int c = tid + i * 256;
        split_hl((row[c] - mu) * inv, yh[(long)r * DMOD + c], yl[(long)r * DMOD + c]);
    }
}

// ---------------- GEMM 128x128: 3-pass split, cp.async 2-stage ----------------
#define GBK   32
#define PADK  40
#define GEMM_SMEM (2 * 4 * 128 * PADK * (int)sizeof(bf16))   // 81920 B

__global__ void __launch_bounds__(256, 2) gemm_pre(
    const bf16* __restrict__ Ah, const bf16* __restrict__ Al, int lda,
    const bf16* __restrict__ Bh, const bf16* __restrict__ Bl, int ldb,
    float* __restrict__ C, int ldc, const float* __restrict__ Res, int K)
{
    extern __shared__ bf16 sm[];
    const int tid  = threadIdx.x;
    const int m0   = blockIdx.y * 128;
    const int n0   = blockIdx.x * 128;
    const int warp = tid >> 5;
    const int wm0  = (warp & 3) * 32;
    const int wn0  = (warp >> 2) * 64;

    wmma::fragment<wmma::accumulator, 16, 16, 16, float> acc[2][4];
    #pragma unroll
    for (int i = 0; i < 2; i++)
        #pragma unroll
        for (int j = 0; j < 4; j++) {
            if (Res) {
                const float* rp = Res + (long)(m0 + wm0 + 16 * i) * ldc
                                      + n0 + wn0 + 16 * j;
                wmma::load_matrix_sync(acc[i][j], rp, ldc, wmma::mem_row_major);
            } else {
                wmma::fill_fragment(acc[i][j], 0.f);
            }
        }

    const bf16* base0 = Ah + (long)m0 * lda;
    const bf16* base1 = Al + (long)m0 * lda;
    const bf16* base2 = Bh + (long)n0 * ldb;
    const bf16* base3 = Bl + (long)n0 * ldb;

    #define LOAD_STAGE(ST, K0)                                                 \
    do {                                                                       \
        bf16* sb = sm + (ST) * (4 * 128 * PADK);                               \
        _Pragma("unroll")                                                      \
        for (int t = 0; t < 8; t++) {                                          \
            int c   = tid + t * 256;                                           \
            int arr = c >> 9;                                                  \
            int rem = c & 511;                                                 \
            int row = rem >> 2;                                                \
            int col = (rem & 3) * 8;                                           \
            const bf16* src =                                                  \
                (arr == 0) ? base0 + (long)row * lda + (K0) + col :            \
                (arr == 1) ? base1 + (long)row * lda + (K0) + col :            \
                (arr == 2) ? base2 + (long)row * ldb + (K0) + col :            \
                             base3 + (long)row * ldb + (K0) + col;             \
            cp16(sb + arr * (128 * PADK) + row * PADK + col, src);             \
        }                                                                      \
    } while (0)

    const int nk = K / GBK;
    LOAD_STAGE(0, 0);
    asm volatile("cp.async.commit_group;\n" ::);

    for (int ks = 0; ks < nk; ks++) {
        asm volatile("cp.async.wait_group 0;\n" ::);
        __syncthreads();
        if (ks + 1 < nk) {
            LOAD_STAGE((ks + 1) & 1, (ks + 1) * GBK);
            asm volatile("cp.async.commit_group;\n" ::);
        }
        bf16* sb  = sm + (ks & 1) * (4 * 128 * PADK);
        bf16* sAh = sb;
        bf16* sAl = sb + 128 * PADK;
        bf16* sBh = sb + 2 * 128 * PADK;
        bf16* sBl = sb + 3 * 128 * PADK;

        #pragma unroll
        for (int k16 = 0; k16 < GBK; k16 += 16) {
            wmma::fragment<wmma::matrix_a, 16, 16, 16, bf16, wmma::row_major> ah[2], al[2];
            #pragma unroll
            for (int i = 0; i < 2; i++) {
                wmma::load_matrix_sync(ah[i], sAh + (wm0 + 16 * i) * PADK + k16, PADK);
                wmma::load_matrix_sync(al[i], sAl + (wm0 + 16 * i) * PADK + k16, PADK);
            }
            #pragma unroll
            for (int j = 0; j < 4; j++) {
                wmma::fragment<wmma::matrix_b, 16, 16, 16, bf16, wmma::col_major> bh, bl;
                wmma::load_matrix_sync(bh, sBh + (wn0 + 16 * j) * PADK + k16, PADK);
                wmma::load_matrix_sync(bl, sBl + (wn0 + 16 * j) * PADK + k16, PADK);
                #pragma unroll
                for (int i = 0; i < 2; i++) {
                    wmma::mma_sync(acc[i][j], ah[i], bl, acc[i][j]);
                    wmma::mma_sync(acc[i][j], al[i], bh, acc[i][j]);
                    wmma::mma_sync(acc[i][j], ah[i], bh, acc[i][j]);
                }
            }
        }
    }

    #pragma unroll
    for (int i = 0; i < 2; i++)
        #pragma unroll
        for (int j = 0; j < 4; j++) {
            float* cp = C + (long)(m0 + wm0 + 16 * i) * ldc + n0 + wn0 + 16 * j;
            wmma::store_matrix_sync(cp, acc[i][j], ldc, wmma::mem_row_major);
        }
}

// ---------------- RoPE + head-major hi/lo split of q,k,v ----------------------
// q pre-scaled by HD^-0.5. dst layout: [h][l][64] (head-major, 128B rows).
__global__ void __launch_bounds__(256) rope_split(
    const float* __restrict__ qkv,
    bf16* __restrict__ qh, bf16* __restrict__ ql,
    bf16* __restrict__ kh, bf16* __restrict__ kl,
    bf16* __restrict__ vh, bf16* __restrict__ vl)
{
    const int idx = blockIdx.x * 256 + threadIdx.x;   // SEQ*NHEAD*32
    if (idx >= SEQ * NHEAD * 32) return;
    const int j = idx & 31;
    const int h = (idx >> 5) & (NHEAD - 1);
    const int l = idx >> 9;

    const float inv_freq = powf(10000.f, -(float)j / 32.f);
    const float ang = (float)l * inv_freq;
    float c, s;
    sincosf(ang, &s, &c);

    const float* qp = qkv + (long)l * (3 * DMOD) + h * HDIM + j;
    const float q1 = qp[0], q2 = qp[32];
    const float k1 = qp[DMOD], k2 = qp[DMOD + 32];
    const float v1 = qp[2 * DMOD], v2 = qp[2 * DMOD + 32];

    const long dst = ((long)h * SEQ + l) * HDIM + j;
    split_hl((q1 * c - q2 * s) * 0.125f, qh[dst],      ql[dst]);
    split_hl((q2 * c + q1 * s) * 0.125f, qh[dst + 32], ql[dst + 32]);
    split_hl(k1 * c - k2 * s,            kh[dst],      kl[dst]);
    split_hl(k2 * c + k1 * s,            kh[dst + 32], kl[dst + 32]);
    split_hl(v1,                         vh[dst],      vl[dst]);
    split_hl(v2,                         vh[dst + 32], vl[dst + 32]);
}

// ---------------- Flash attention: pre-split head-major inputs ----------------
#define QSTR 80
#define FSTR 68
#define AT2_SMEM (4 * 64 * QSTR * 2 + 2 * 64 * FSTR * 4)   // 75776 B

__global__ void __launch_bounds__(256, 2) attn2(
    const bf16* __restrict__ Qh, const bf16* __restrict__ Ql,
    const bf16* __restrict__ Kh, const bf16* __restrict__ Kl,
    const bf16* __restrict__ Vh, const bf16* __restrict__ Vl,
    bf16* __restrict__ outh, bf16* __restrict__ outl)
{
    extern __shared__ char smraw[];
    bf16* sKh = (bf16*)smraw;
    bf16* sKl = sKh + 64 * QSTR;
    bf16* sVh = sKl + 64 * QSTR;
    bf16* sVl = sVh + 64 * QSTR;
    float* Sf = (float*)(sVl + 64 * QSTR);
    float* Of = Sf + 64 * FSTR;
    bf16* Ph = sKh;       // alias: P overwrites K after S is computed
    bf16* Pl = sKl;

    const int h     = blockIdx.x;
    const int qb    = (int)gridDim.y - 1 - (int)blockIdx.y;  // long rows first
    const int tid   = threadIdx.x;
    const int warp  = tid >> 5;
    const int qbase = qb * 64;
    const int rt    = warp >> 1;
    const int chalf = (warp & 1) * 32;

    // ---- stage Q via sKh/sKl, load fragments once
    const long qoff = ((long)h * SEQ + qbase) * HDIM;
    #pragma unroll
    for (int t = 0; t < 2; t++) {
        int c = tid + t * 256;
        int row = c >> 3, ch = (c & 7) * 8;
        cp16(sKh + row * QSTR + ch, Qh + qoff + row * HDIM + ch);
        cp16(sKl + row * QSTR + ch, Ql + qoff + row * HDIM + ch);
    }
    asm volatile("cp.async.commit_group;\n" ::);
    asm volatile("cp.async.wait_group 0;\n" ::);
    __syncthreads();

    wmma::fragment<wmma::matrix_a, 16, 16, 16, bf16, wmma::row_major> qhf[4], qlf[4];
    #pragma unroll
    for (int ks = 0; ks < 4; ks++) {
        wmma::load_matrix_sync(qhf[ks], sKh + rt * 16 * QSTR + ks * 16, QSTR);
        wmma::load_matrix_sync(qlf[ks], sKl + rt * 16 * QSTR + ks * 16, QSTR);
    }
    for (int i = tid; i < 64 * FSTR; i += 256) Of[i] = 0.f;
    __syncthreads();   // Q frags read; sKh/sKl now reusable

    const int r  = tid >> 2;
    const int cs = (tid & 3) * 16;
    float mrow = -1e30f, lsum = 0.f, alpha = 0.f;

    for (int kb = 0; kb <= qb; kb++) {
        const long koff = ((long)h * SEQ + kb * 64) * HDIM;
        #pragma unroll
        for (int t = 0; t < 2; t++) {
            int c = tid + t * 256;
            int row = c >> 3, ch = (c & 7) * 8;
            cp16(sKh + row * QSTR + ch, Kh + koff + row * HDIM + ch);
            cp16(sKl + row * QSTR + ch, Kl + koff + row * HDIM + ch);
            cp16(sVh + row * QSTR + ch, Vh + koff + row * HDIM + ch);
            cp16(sVl + row * QSTR + ch, Vl + koff + row * HDIM + ch);
        }
        asm volatile("cp.async.commit_group;\n" ::);
        asm volatile("cp.async.wait_group 0;\n" ::);
        __syncthreads();

        // ---- S = Q K^T (3-pass split)
        #pragma unroll
        for (int ct = 0; ct < 2; ct++) {
            const int col0 = chalf + ct * 16;
            wmma::fragment<wmma::accumulator, 16, 16, 16, float> acc;
            wmma::fill_fragment(acc, 0.f);
            #pragma unroll
            for (int ks = 0; ks < 4; ks++) {
                wmma::fragment<wmma::matrix_b, 16, 16, 16, bf16, wmma::col_major> bh, bl;
                wmma::load_matrix_sync(bh, sKh + col0 * QSTR + ks * 16, QSTR);
                wmma::load_matrix_sync(bl, sKl + col0 * QSTR + ks * 16, QSTR);
                wmma::mma_sync(acc, qhf[ks], bl, acc);
                wmma::mma_sync(acc, qlf[ks], bh, acc);
                wmma::mma_sync(acc, qhf[ks], bh, acc);
            }
            wmma::store_matrix_sync(Sf + rt * 16 * FSTR + col0, acc, FSTR,
                                    wmma::mem_row_major);
        }
        __syncthreads();

        // ---- online softmax (4 threads per row)
        float s[16];
        #pragma unroll
        for (int j = 0; j < 16; j++) s[j] = Sf[r * FSTR + cs + j];
        if (kb == qb) {
            const int kbase = kb * 64;
            #pragma unroll
            for (int j = 0; j < 16; j++)
                if (kbase + cs + j > qbase + r) s[j] = -1e30f;
        }
        float mloc = s[0];
        #pragma unroll
        for (int j = 1; j < 16; j++) mloc = fmaxf(mloc, s[j]);
        mloc = fmaxf(mloc, __shfl_xor_sync(0xffffffffu, mloc, 1));
        mloc = fmaxf(mloc, __shfl_xor_sync(0xffffffffu, mloc, 2));
        const float mnew = fmaxf(mrow, mloc);
        alpha = __expf(mrow - mnew);

        float ps = 0.f;
        #pragma unroll
        for (int j = 0; j < 16; j++) {
            float p = __expf(s[j] - mnew);
            ps += p;
            split_hl(p, Ph[r * QSTR + cs + j], Pl[r * QSTR + cs + j]);
        }
        ps += __shfl_xor_sync(0xffffffffu, ps, 1);
        ps += __shfl_xor_sync(0xffffffffu, ps, 2);
        lsum = lsum * alpha + ps;
        mrow = mnew;
        __syncthreads();

        // ---- T = P V (3-pass split) -> Sf
        #pragma unroll
        for (int ct = 0; ct < 2; ct++) {
            const int col0 = chalf + ct * 16;
            wmma::fragment<wmma::accumulator, 16, 16, 16, float> acc;
            wmma::fill_fragment(acc, 0.f);
            #pragma unroll
            for (int js = 0; js < 4; js++) {
                wmma::fragment<wmma::matrix_a, 16, 16, 16, bf16, wmma::row_major> ph, pl;
                wmma::load_matrix_sync(ph, Ph + rt * 16 * QSTR + js * 16, QSTR);
                wmma::load_matrix_sync(pl, Pl + rt * 16 * QSTR + js * 16, QSTR);
                wmma::fragment<wmma::matrix_b, 16, 16, 16, bf16, wmma::row_major> vh, vl;
                wmma::load_matrix_sync(vh, sVh + js * 16 * QSTR + col0, QSTR);
                wmma::load_matrix_sync(vl, sVl + js * 16 * QSTR + col0, QSTR);
                wmma::mma_sync(acc, ph, vl, acc);
                wmma::mma_sync(acc, pl, vh, acc);
                wmma::mma_sync(acc, ph, vh, acc);
            }
            wmma::store_matrix_sync(Sf + rt * 16 * FSTR + col0, acc, FSTR,
                                    wmma::mem_row_major);
        }
        __syncthreads();

        #pragma unroll
        for (int j = 0; j < 16; j++) {
            int o = r * FSTR + cs + j;
            Of[o] = Of[o] * alpha + Sf[o];
        }
        __syncthreads();
    }

    const float invl = 1.f / lsum;
    const long obase = (long)(qbase + r) * DMOD + h * HDIM + cs;
    #pragma unroll
    for (int j = 0; j < 16; j++)
        split_hl(Of[r * FSTR + cs + j] * invl, outh[obase + j], outl[obase + j]);
}

// ---------------- SwiGLU -> bf16 hi/lo -----------------------------------------
__global__ void __launch_bounds__(256) swiglu_kernel(const float* __restrict__ g,
                                                     bf16* __restrict__ oh,
                                                     bf16* __restrict__ ol) {
    const int idx = blockIdx.x * 256 + threadIdx.x;
    if (idx >= SEQ * (DMLP / 2)) return;
    const int rw = idx >> 12;
    const int c  = idx & 4095;
    const float x1 = g[(long)rw * DMLP + c];
    const float x2 = g[(long)rw * DMLP + (DMLP / 2) + c];
    const float sig = 1.f / (1.f + __expf(-x2));
    split_hl(x2 * sig * x1, oh[idx], ol[idx]);
}

// ---------------- launch --------------------------------------------------------
extern "C" void kernel_launch(void* const* d_in, const int* in_sizes, int n_in,
                              void* d_out, int out_size) {
    const float* x      = (const float*)d_in[0];
    const float* W_attn = (const float*)d_in[2];
    const float* W_out  = (const float*)d_in[3];
    const float* W_ffp  = (const float*)d_in[4];
    const float* W_ffo  = (const float*)d_in[5];
    float* out = (float*)d_out;

    float *qkv, *h, *gbuf;
    bf16 *xnh, *xnl, *ath, *atl, *hnh, *hnl, *mph, *mpl;
    bf16 *qh, *ql, *kh, *kl, *vh, *vl;
    bf16 *Wah, *Wal, *Woh, *Wol, *Wph, *Wpl, *Wfh, *Wfl;
    cudaGetSymbolAddress((void**)&qkv, g_qkv);
    cudaGetSymbolAddress((void**)&h,   g_h);
    cudaGetSymbolAddress((void**)&gbuf,g_g);
    cudaGetSymbolAddress((void**)&xnh, g_xnh); cudaGetSymbolAddress((void**)&xnl, g_xnl);
    cudaGetSymbolAddress((void**)&ath, g_ath); cudaGetSymbolAddress((void**)&atl, g_atl);
    cudaGetSymbolAddress((void**)&hnh, g_hnh); cudaGetSymbolAddress((void**)&hnl, g_hnl);
    cudaGetSymbolAddress((void**)&mph, g_mph); cudaGetSymbolAddress((void**)&mpl, g_mpl);
    cudaGetSymbolAddress((void**)&qh,  g_qh);  cudaGetSymbolAddress((void**)&ql,  g_ql);
    cudaGetSymbolAddress((void**)&kh,  g_kh);  cudaGetSymbolAddress((void**)&kl,  g_kl);
    cudaGetSymbolAddress((void**)&vh,  g_vh);  cudaGetSymbolAddress((void**)&vl,  g_vl);
    cudaGetSymbolAddress((void**)&Wah, g_Wah); cudaGetSymbolAddress((void**)&Wal, g_Wal);
    cudaGetSymbolAddress((void**)&Woh, g_Woh); cudaGetSymbolAddress((void**)&Wol, g_Wol);
    cudaGetSymbolAddress((void**)&Wph, g_Wph); cudaGetSymbolAddress((void**)&Wpl, g_Wpl);
    cudaGetSymbolAddress((void**)&Wfh, g_Wfh); cudaGetSymbolAddress((void**)&Wfl, g_Wfl);

    cudaFuncSetAttribute(attn2,
                         cudaFuncAttributeMaxDynamicSharedMemorySize, AT2_SMEM);
    cudaFuncSetAttribute(gemm_pre,
                         cudaFuncAttributeMaxDynamicSharedMemorySize, GEMM_SMEM);

    // weight splits
    { int n = 3 * DMOD * DMOD; cvt_hilo<<<n / 8 / 256, 256>>>(W_attn, Wah, Wal, n); }
    { int n = DMOD * DMOD;     cvt_hilo<<<n / 8 / 256, 256>>>(W_out,  Woh, Wol, n); }
    { int n = DMLP * DMOD;     cvt_hilo<<<n / 8 / 256, 256>>>(W_ffp,  Wph, Wpl, n); }
    { int n = DMOD * DMLP / 2; cvt_hilo<<<n / 8 / 256, 256>>>(W_ffo,  Wfh, Wfl, n); }

    // 1) xn = LN(x)
    ln_kernel<<<SEQ, 256>>>(x, xnh, xnl);

    // 2) qkv = xn @ W_attn^T
    gemm_pre<<<dim3(3 * DMOD / 128, SEQ / 128), 256, GEMM_SMEM>>>(
        xnh, xnl, DMOD, Wah, Wal, DMOD, qkv, 3 * DMOD, nullptr, DMOD);

    // 3) RoPE + head-major hi/lo split
    rope_split<<<(SEQ * NHEAD * 32 + 255) / 256, 256>>>(qkv, qh, ql, kh, kl, vh, vl);

    // 4) attention
    attn2<<<dim3(NHEAD, SEQ / 64), 256, AT2_SMEM>>>(qh, ql, kh, kl, vh, vl, ath, atl);

    // 5) h = attn @ W_out^T + x
    gemm_pre<<<dim3(DMOD / 128, SEQ / 128), 256, GEMM_SMEM>>>(
        ath, atl, DMOD, Woh, Wol, DMOD, h, DMOD, x, DMOD);

    // 6) hn = LN(h)
    ln_kernel<<<SEQ, 256>>>(h, hnh, hnl);

    // 7) g = hn @ W_ffp^T
    gemm_pre<<<dim3(DMLP / 128, SEQ / 128), 256, GEMM_SMEM>>>(
        hnh, hnl, DMOD, Wph, Wpl, DMOD, gbuf, DMLP, nullptr, DMOD);

    // 8) mlp = silu(g2)*g1
    swiglu_kernel<<<(SEQ * (DMLP / 2) + 255) / 256, 256>>>(gbuf, mph, mpl);

    // 9) out = mlp @ W_ffo^T + h
    gemm_pre<<<dim3(DMOD / 128, SEQ / 128), 256, GEMM_SMEM>>>(
        mph, mpl, DMLP / 2, Wfh, Wfl, DMLP / 2, out, DMOD, h, DMLP / 2);
}